// round 14
// baseline (speedup 1.0000x reference)
#include <cuda_runtime.h>
#include <cuda_bf16.h>
#include <math.h>
#include <stdint.h>

#define NSP   8192
#define LEN   512
#define HD    768
#define MAXW  30
#define FFD   3000
#define MD    2324      // 3*768+20
#define KTOP  204
#define CANT  50
#define NEG9  (-1e9f)

#define TRI   1225      // 50*49/2
#define VROWS 8925      // valid pairs: sum min(i,50)
#define VPAD  8960      // 70 * 128

#define KPAD  2368      // MD padded to multiple of 64
#define K16   1184      // KPAD/2 : b16 units per fp8 row
#define SW16  256       // LEN/2  : b16 units per fp8 SW row
#define FFP   3072      // FFD padded to multiple of 128
#define C2N   2432      // MD padded to multiple of 128 (src gemm N)
#define NCB   24        // FFP/128
#define BM    128
#define BN    128
#define BKK   32
#define PSEC  ((size_t)LEN * FFP)

#define STAGES 4
#define A_PITCH 40
#define B_PITCH 136
#define A_BYTES (BM * A_PITCH * 2)        // 10240
#define B_BYTES (BKK * B_PITCH * 2)       // 8704
#define STAGE_BYTES (A_BYTES + B_BYTES)   // 18944
#define DSMEM (STAGES * STAGE_BYTES)      // 75776
#define DSMEM_ALL (DSMEM + 128 * 16)      // + rowsum/sRi/sRp/sRc tail = 77824

// mega_prep section boundaries (linear block index)
#define S0E 7104     // conv_w0   : d(2368) x f4grp(3)
#define S1E 49728    // conv_aw08 : sec(3) x k16(1184) x ngrp(12)
#define S2E 56832    // conv_c2   : d(2368) x f4grp(3)
#define S3E 57216    // conv_h    : 384
#define S4E 57246    // wproj     : 30
#define S5E 57426    // width_scores : 30 x 6
#define S6E 57490    // tok_score : 64 (8 tokens/block)
#define S7E 57550    // featcomb direct : 60

// ---------------- scratch (static device globals; zero-initialized) ----------------
__device__ __nv_bfloat16  g_w0h[(size_t)KPAD * FFP];       // mention_w0 bf16
__device__ uint16_t       g_aw08[3 * (size_t)K16 * FFP];   // ant_w0 a,b,c fp8 pair-interleaved x64
__device__ __nv_bfloat16  g_c2h[(size_t)KPAD * C2N];       // c2_w bf16 padded
__device__ uint16_t       g_pair8[(size_t)VPAD * K16];     // compact pair products, fp8
__device__ __nv_bfloat16  g_hh[(size_t)LEN * HD];          // h bf16
__device__ uint8_t        g_sw8[(size_t)NSP * LEN];        // span softmax weights fp8 x64
__device__ __nv_bfloat16  g_Pb[3 * PSEC];                  // P_s | P_e | P_h  (bf16)
__device__ uint16_t       g_ph8[(size_t)SW16 * FFP];       // P_h fp8 pair-interleaved x64
__device__ __nv_bfloat16  g_srch[(size_t)256 * KPAD];      // src bf16 (padding stays 0)
__device__ __nv_bfloat16  g_topbT[(size_t)KPAD * 256];     // top_base^T bf16
__device__ __nv_bfloat16  g_wmb[MAXW * FFP];               // width_emb @ W0_w (bf16)
__device__ float g_tok[LEN];
__device__ float g_wts[(size_t)NSP * 32];                  // fp32 softmax weights
__device__ int   g_w[NSP];
__device__ int   g_s[NSP];
__device__ int   g_e[NSP];
__device__ float g_m[NSP];
__device__ float g_wpart[MAXW * 6];
__device__ int   g_topidx[KTOP];
__device__ float g_topm[KTOP];
__device__ int   g_topspk[KTOP];
__device__ int   g_topseg[KTOP];
__device__ __nv_bfloat16 g_topbaseh[(size_t)256 * KPAD];   // rows 204..255 stay 0
__device__ uint16_t      g_topb8[(size_t)256 * K16];       // top_base fp8 x8 (rows 204..255 zero)
__device__ float g_cp[KTOP * KTOP];
__device__ float g_antsc[KTOP * CANT];
__device__ int   g_antpos[KTOP * CANT];
__device__ __nv_bfloat16 g_uabb[2 * (size_t)KTOP * FFP];   // UA | UB (bf16)
__device__ __nv_bfloat16 g_featb[60 * FFP];                // combined feature rows (bf16)
__device__ float g_part[(size_t)NSP * NCB];

// orderable key: primary = value descending, secondary = index ascending
__device__ __forceinline__ unsigned long long make_key(float v, unsigned idx) {
    unsigned u = __float_as_uint(v);
    u = (u & 0x80000000u) ? ~u : (u | 0x80000000u);
    return ((unsigned long long)u << 32) | (unsigned)(0xFFFFFFFFu - idx);
}
__device__ __forceinline__ int key_idx(unsigned long long k) {
    return (int)(0xFFFFFFFFu - (unsigned)(k & 0xFFFFFFFFu));
}

// compact pair index t -> (i, c) with c < min(i, CANT)
__device__ __forceinline__ void pair_decode(int t, int& i, int& c) {
    if (t < TRI) {
        int ii = (int)((sqrtf(8.f * t + 1.f) + 1.f) * 0.5f);
        while (ii * (ii - 1) / 2 > t) ii--;
        while ((ii + 1) * ii / 2 <= t) ii++;
        i = ii; c = t - ii * (ii - 1) / 2;
    } else {
        int u = t - TRI;
        i = 50 + u / 50; c = u % 50;
        if (i > KTOP - 1) { i = KTOP - 1; c = CANT - 1; }
    }
}
__device__ __forceinline__ int pair_off(int i) {
    return (i <= 50) ? i * (i - 1) / 2 : TRI + (i - 50) * 50;
}

// ---------------- PTX helpers ----------------
__device__ __forceinline__ void cp_async16(void* s, const void* g) {
    uint32_t sa = (uint32_t)__cvta_generic_to_shared(s);
    asm volatile("cp.async.cg.shared.global [%0], [%1], 16;" :: "r"(sa), "l"(g));
}
__device__ __forceinline__ void cp_commit() { asm volatile("cp.async.commit_group;"); }
template<int N> __device__ __forceinline__ void cp_wait() {
    asm volatile("cp.async.wait_group %0;" :: "n"(N));
}
__device__ __forceinline__ void ldsm_x4(uint32_t* r, uint32_t addr) {
    asm volatile("ldmatrix.sync.aligned.m8n8.x4.shared.b16 {%0,%1,%2,%3}, [%4];"
                 : "=r"(r[0]), "=r"(r[1]), "=r"(r[2]), "=r"(r[3]) : "r"(addr));
}
__device__ __forceinline__ void ldsm_x4_t(uint32_t* r, uint32_t addr) {
    asm volatile("ldmatrix.sync.aligned.m8n8.x4.trans.shared.b16 {%0,%1,%2,%3}, [%4];"
                 : "=r"(r[0]), "=r"(r[1]), "=r"(r[2]), "=r"(r[3]) : "r"(addr));
}
__device__ __forceinline__ void mma_bf16(float* c, const uint32_t* a, uint32_t b0, uint32_t b1) {
    asm volatile("mma.sync.aligned.m16n8k16.row.col.f32.bf16.bf16.f32 "
                 "{%0,%1,%2,%3}, {%4,%5,%6,%7}, {%8,%9}, {%0,%1,%2,%3};"
                 : "+f"(c[0]), "+f"(c[1]), "+f"(c[2]), "+f"(c[3])
                 : "r"(a[0]), "r"(a[1]), "r"(a[2]), "r"(a[3]), "r"(b0), "r"(b1));
}
__device__ __forceinline__ void mma_fp8(float* c, const uint32_t* a, uint32_t b0, uint32_t b1) {
    asm volatile("mma.sync.aligned.m16n8k32.row.col.f32.e4m3.e4m3.f32 "
                 "{%0,%1,%2,%3}, {%4,%5,%6,%7}, {%8,%9}, {%0,%1,%2,%3};"
                 : "+f"(c[0]), "+f"(c[1]), "+f"(c[2]), "+f"(c[3])
                 : "r"(a[0]), "r"(a[1]), "r"(a[2]), "r"(a[3]), "r"(b0), "r"(b1));
}
// pack two floats into e4m3x2: low byte = lo, high byte = hi
__device__ __forceinline__ uint16_t cvt_e4m3x2(float lo, float hi) {
    uint16_t d;
    asm("cvt.rn.satfinite.e4m3x2.f32 %0, %1, %2;" : "=h"(d) : "f"(hi), "f"(lo));
    return d;
}

// ---------------- mega prep: conversions + wproj + width_scores + tok_score + featcomb ----------------
__global__ void mega_prep(const float* __restrict__ mention_w0, const float* __restrict__ ant_w0,
                          const float* __restrict__ c2w, const float* __restrict__ h,
                          const float* __restrict__ w_head, const float* __restrict__ b_head,
                          const float* __restrict__ width_emb, const float* __restrict__ wprior,
                          const float* __restrict__ ww0, const float* __restrict__ wb0,
                          const float* __restrict__ ww1,
                          const float* __restrict__ spk_emb, const float* __restrict__ gen_emb,
                          const float* __restrict__ dist_emb, const float* __restrict__ seg_emb,
                          const int* __restrict__ gen_ids)
{
    __shared__ float shA[256];
    __shared__ float shB[80];
    int b = blockIdx.x;
    int tid = threadIdx.x;

    if (b < S0E) {                         // conv_w0 (bf16)
        int d = b / 3, fx = b % 3;
        int f4 = fx * 256 + tid;
        if (f4 >= FFP / 4) return;
        float4 v = make_float4(0.f, 0.f, 0.f, 0.f);
        if (d < MD && f4 < FFD / 4)
            v = *(const float4*)(mention_w0 + (size_t)d * FFD + f4 * 4);
        __nv_bfloat16 o[4] = { __float2bfloat16(v.x), __float2bfloat16(v.y),
                               __float2bfloat16(v.z), __float2bfloat16(v.w) };
        *(uint64_t*)(g_w0h + (size_t)d * FFP + f4 * 4) = *(uint64_t*)o;
    } else if (b < S1E) {                  // conv_aw08 (fp8 x64 pair-interleaved)
        int id = b - S0E;
        int s = id / (12 * K16);
        int rem = id % (12 * K16);
        int k16 = rem / 12, nx = rem % 12;
        int n = nx * 256 + tid;
        if (n >= FFP) return;
        int k0 = 2 * k16, k1 = 2 * k16 + 1;
        float lo = 0.f, hi = 0.f;
        if (n < FFD) {
            if (k0 < MD) lo = ant_w0[(size_t)(s * MD + k0) * FFD + n] * 64.f;
            if (k1 < MD) hi = ant_w0[(size_t)(s * MD + k1) * FFD + n] * 64.f;
        }
        g_aw08[(size_t)s * K16 * FFP + (size_t)k16 * FFP + n] = cvt_e4m3x2(lo, hi);
    } else if (b < S2E) {                  // conv_c2 (bf16)
        int id = b - S1E;
        int d = id / 3, fx = id % 3;
        int f4 = fx * 256 + tid;
        if (f4 >= C2N / 4) return;
        float4 v = make_float4(0.f, 0.f, 0.f, 0.f);
        if (d < MD) {
            float t[4];
            #pragma unroll
            for (int q = 0; q < 4; q++)
                t[q] = (f4 * 4 + q < MD) ? c2w[(size_t)d * MD + f4 * 4 + q] : 0.f;
            v = make_float4(t[0], t[1], t[2], t[3]);
        }
        __nv_bfloat16 o[4] = { __float2bfloat16(v.x), __float2bfloat16(v.y),
                               __float2bfloat16(v.z), __float2bfloat16(v.w) };
        *(uint64_t*)(g_c2h + (size_t)d * C2N + f4 * 4) = *(uint64_t*)o;
    } else if (b < S3E) {                  // conv_h (bf16)
        size_t i4 = (size_t)(b - S2E) * 256 + tid;
        if (i4 >= (size_t)LEN * HD / 4) return;
        float4 v = *(const float4*)(h + i4 * 4);
        __nv_bfloat16 o[4] = { __float2bfloat16(v.x), __float2bfloat16(v.y),
                               __float2bfloat16(v.z), __float2bfloat16(v.w) };
        *(uint64_t*)(g_hh + i4 * 4) = *(uint64_t*)o;
    } else if (b < S4E) {                  // wproj -> g_wmb (bf16)
        int w = b - S3E;
        if (tid < 20) shB[tid] = width_emb[w * 20 + tid];
        __syncthreads();
        for (int f = tid; f < FFP; f += 256) {
            float acc = 0.f;
            if (f < FFD) {
                #pragma unroll
                for (int k = 0; k < 20; k++)
                    acc += shB[k] * mention_w0[(size_t)(3 * HD + k) * FFD + f];
            }
            g_wmb[(size_t)w * FFP + f] = __float2bfloat16(acc);
        }
    } else if (b < S5E) {                  // width_scores -> g_wpart
        int id = b - S4E;
        int w = id / 6, seg = id % 6;
        if (tid < 20) shB[tid] = wprior[w * 20 + tid];
        __syncthreads();
        float acc = 0.f;
        int f0 = seg * 512;
        int f1 = min(f0 + 512, FFD);
        for (int f = f0 + tid; f < f1; f += 256) {
            float d = wb0[f];
            #pragma unroll
            for (int k = 0; k < 20; k++) d += shB[k] * ww0[k * FFD + f];
            acc += fmaxf(d, 0.f) * ww1[f];
        }
        shA[tid] = acc;
        __syncthreads();
        for (int o = 128; o > 0; o >>= 1) { if (tid < o) shA[tid] += shA[tid + o]; __syncthreads(); }
        if (tid == 0) g_wpart[w * 6 + seg] = shA[0];
    } else if (b < S6E) {                  // tok_score (8 tokens per block)
        int t = (b - S5E) * 8 + (tid >> 5);
        int lane = tid & 31;
        if (t >= LEN) return;
        const float* row = h + (size_t)t * HD;
        float acc = 0.f;
        for (int c = lane; c < HD; c += 32) acc += row[c] * w_head[c];
        #pragma unroll
        for (int o = 16; o > 0; o >>= 1) acc += __shfl_down_sync(0xffffffffu, acc, o);
        if (lane == 0) g_tok[t] = acc + b_head[0];
    } else if (b < S7E) {                  // featcomb direct -> g_featb (bf16)
        int code = b - S6E;
        int s = code / 30, bk = (code / 3) % 10, ds = code % 3;
        if (tid < 20) {
            int g = gen_ids[0];
            shB[tid]      = spk_emb[s * 20 + tid];
            shB[20 + tid] = gen_emb[g * 20 + tid];
            shB[40 + tid] = dist_emb[bk * 20 + tid];
            shB[60 + tid] = seg_emb[ds * 20 + tid];
        }
        __syncthreads();
        for (int f = tid; f < FFP; f += 256) {
            float acc = 0.f;
            if (f < FFD) {
                #pragma unroll
                for (int k = 0; k < 80; k++)
                    acc += shB[k] * ant_w0[(size_t)(3 * MD + k) * FFD + f];
            }
            g_featb[(size_t)code * FFP + f] = __float2bfloat16(acc);
        }
    }
}

// P_h (bf16 section 2 of g_Pb) -> fp8 pair-interleaved x64
__global__ void conv_ph8()
{
    int f = blockIdx.x * 256 + threadIdx.x;      // 0..FFP-1
    int k16 = blockIdx.y;                        // 0..SW16-1
    if (f >= FFP) return;
    float lo = __bfloat162float(g_Pb[2 * PSEC + (size_t)(2 * k16) * FFP + f]) * 64.f;
    float hi = __bfloat162float(g_Pb[2 * PSEC + (size_t)(2 * k16 + 1) * FFP + f]) * 64.f;
    g_ph8[(size_t)k16 * FFP + f] = cvt_e4m3x2(lo, hi);
}
__global__ void transp_topb()
{
    __shared__ __nv_bfloat16 t[32][33];
    int k0 = blockIdx.x * 32, j0 = blockIdx.y * 32;
    int tx = threadIdx.x, ty = threadIdx.y;   // (32, 8)
    #pragma unroll
    for (int r = 0; r < 4; r++)
        t[ty + r * 8][tx] = g_topbaseh[(size_t)(j0 + ty + r * 8) * KPAD + k0 + tx];
    __syncthreads();
    #pragma unroll
    for (int r = 0; r < 4; r++)
        g_topbT[(size_t)(k0 + ty + r * 8) * 256 + j0 + tx] = t[tx][ty + r * 8];
}

// ---------------- span softmax weights (fp8 x64 rows) ----------------
__global__ void span_prep(const int* __restrict__ spans)
{
    int n = blockIdx.x * 8 + (threadIdx.x >> 5);
    int lane = threadIdx.x & 31;
    if (n >= NSP) return;
    int s = spans[2 * n], e = spans[2 * n + 1];
    s = min(max(s, 0), LEN - 1);
    e = min(max(e, 0), LEN - 1);
    int w = e - s + 1;
    if (w < 1) w = 1;
    if (w > MAXW) w = MAXW;
    if (lane == 0) { g_s[n] = s; g_e[n] = e; g_w[n] = w; }
    float v = (lane < w) ? g_tok[s + lane] : -1e30f;
    float mx = v;
    #pragma unroll
    for (int o = 16; o > 0; o >>= 1) mx = fmaxf(mx, __shfl_xor_sync(0xffffffffu, mx, o));
    float p = (lane < w) ? expf(v - mx) : 0.f;
    float sm = p;
    #pragma unroll
    for (int o = 16; o > 0; o >>= 1) sm += __shfl_xor_sync(0xffffffffu, sm, o);
    float wt = p / sm;
    g_wts[(size_t)n * 32 + lane] = wt;
    if (lane < w) {
        uint16_t pk = cvt_e4m3x2(wt * 64.f, 0.f);
        g_sw8[(size_t)n * LEN + s + lane] = (uint8_t)(pk & 0xFF);
    }
}

// ---------------- tensor-core GEMM body (inlined; cp.async 4-stage) ----------------
// EPI 1: fused fine epilogue  (+ uabb[i] + uabb[K+p] + featb[code]) -> g_part
// EPI 2: raw C (*scale, +optional bias) -> outC (fp32 or bf16 per OUT16)
// EPI 3: fused mention epilogue (+ Pb_s[s] + Pb_e[e] + wmb[w-1])    -> g_part
// EPI 4: cp epilogue: + topm[r] + topm[f], tril mask -> g_cp (fp32)
template<int EPI, int FP8, int OUT16>
__device__ __forceinline__ void gemm_body(
    const __nv_bfloat16* __restrict__ A, int lda,
    const __nv_bfloat16* __restrict__ Bg, int ldb,
    const float* __restrict__ b0v, const float* __restrict__ w1v,
    void* __restrict__ outCv, int ldc,
    int kIter, int R, int maxC, float scale, char* smem)
{
    float* rowsum = (float*)(smem + DSMEM);
    int* sRi = (int*)(rowsum + 128);
    int* sRp = sRi + 128;
    int* sRc = sRp + 128;

    int tid = threadIdx.x;
    int lane = tid & 31, warp = tid >> 5;
    int wm = warp >> 2, wn = warp & 3;
    int row0 = blockIdx.y * BM, col0 = blockIdx.x * BN;

    if (tid < BM) {
        rowsum[tid] = 0.f;
        int r = row0 + tid;
        if (EPI == 1) {
            int i, c;
            pair_decode(r, i, c);
            int p = g_antpos[i * CANT + c];
            sRi[tid] = i; sRp[tid] = p;
            int same = (g_topspk[i] == g_topspk[p]) ? 1 : 0;
            int off = i - p; if (off < 0) off = 0;
            int bk = off >= 64 ? 9 : off >= 32 ? 8 : off >= 16 ? 7 : off >= 8 ? 6 : off >= 5 ? 5 : off;
            int ds = g_topseg[i] - g_topseg[p]; ds = ds < 0 ? 0 : (ds > 2 ? 2 : ds);
            sRc[tid] = (same * 10 + bk) * 3 + ds;
        }
        if (EPI == 3) {
            sRi[tid] = g_s[r]; sRp[tid] = g_e[r]; sRc[tid] = g_w[r] - 1;
        }
    }
    __syncthreads();

    float acc[4][4][4];
    #pragma unroll
    for (int a = 0; a < 4; a++)
        #pragma unroll
        for (int b = 0; b < 4; b++)
            #pragma unroll
            for (int c = 0; c < 4; c++) acc[a][b][c] = 0.f;

    auto issue = [&](int kt) {
        int k0 = kt * BKK;
        char* sa = smem + (size_t)(kt % STAGES) * STAGE_BYTES;
        char* sb = sa + A_BYTES;
        #pragma unroll
        for (int v = 0; v < 2; v++) {
            int idx = tid + v * 256;
            int arow = idx >> 2, aseg = idx & 3;
            cp_async16(sa + (size_t)(arow * A_PITCH + aseg * 8) * 2,
                       A + (size_t)(row0 + arow) * lda + k0 + aseg * 8);
            int brow = idx >> 4, bseg = idx & 15;
            cp_async16(sb + (size_t)(brow * B_PITCH + bseg * 8) * 2,
                       Bg + (size_t)(k0 + brow) * ldb + col0 + bseg * 8);
        }
    };

    #pragma unroll
    for (int s = 0; s < STAGES - 1; s++) { issue(s); cp_commit(); }

    for (int kt = 0; kt < kIter; kt++) {
        cp_wait<STAGES - 2>();
        __syncthreads();
        if (kt + STAGES - 1 < kIter) issue(kt + STAGES - 1);
        cp_commit();

        int cur = kt % STAGES;
        const __nv_bfloat16 (*As)[A_PITCH] =
            (const __nv_bfloat16 (*)[A_PITCH])(smem + (size_t)cur * STAGE_BYTES);
        const __nv_bfloat16 (*Bs)[B_PITCH] =
            (const __nv_bfloat16 (*)[B_PITCH])(smem + (size_t)cur * STAGE_BYTES + A_BYTES);

        #pragma unroll
        for (int kk = 0; kk < BKK; kk += 16) {
            uint32_t af[4][4];
            #pragma unroll
            for (int mf = 0; mf < 4; mf++) {
                uint32_t addr = (uint32_t)__cvta_generic_to_shared(
                    &As[wm * 64 + mf * 16 + (lane & 15)][kk + ((lane >> 4) << 3)]);
                ldsm_x4(af[mf], addr);
            }
            uint32_t bfr[2][4];
            #pragma unroll
            for (int g = 0; g < 2; g++) {
                int krow = kk + (lane & 7) + ((lane & 8) ? 8 : 0);
                int bcol = wn * 32 + g * 16 + ((lane & 16) ? 8 : 0);
                uint32_t addr = (uint32_t)__cvta_generic_to_shared(&Bs[krow][bcol]);
                ldsm_x4_t(bfr[g], addr);
            }
            #pragma unroll
            for (int mf = 0; mf < 4; mf++)
                #pragma unroll
                for (int nf = 0; nf < 4; nf++) {
                    if (FP8)
                        mma_fp8(acc[mf][nf], af[mf], bfr[nf >> 1][(nf & 1) * 2],
                                bfr[nf >> 1][(nf & 1) * 2 + 1]);
                    else
                        mma_bf16(acc[mf][nf], af[mf], bfr[nf >> 1][(nf & 1) * 2],
                                 bfr[nf >> 1][(nf & 1) * 2 + 1]);
                }
        }
        __syncthreads();
    }

    if (EPI == 2 || EPI == 4) {
        float* outF = (float*)outCv;
        __nv_bfloat16* outH = (__nv_bfloat16*)outCv;
        #pragma unroll
        for (int mf = 0; mf < 4; mf++)
            #pragma unroll
            for (int rr = 0; rr < 2; rr++) {
                int r = row0 + wm * 64 + mf * 16 + (lane >> 2) + rr * 8;
                if (r >= R) continue;
                #pragma unroll
                for (int nf = 0; nf < 4; nf++) {
                    int f = col0 + wn * 32 + nf * 8 + (lane & 3) * 2;
                    #pragma unroll
                    for (int c = 0; c < 2; c++) {
                        if (f + c < maxC) {
                            float v = acc[mf][nf][rr * 2 + c] * scale;
                            if (EPI == 4) {
                                v += g_topm[r] + g_topm[f + c];
                                if (f + c >= r) v = NEG9;
                            } else if (b0v) v += b0v[f + c];
                            if (OUT16) outH[(size_t)r * ldc + f + c] = __float2bfloat16(v);
                            else       outF[(size_t)r * ldc + f + c] = v;
                        }
                    }
                }
            }
        return;
    }

    // fused epilogue: relu(acc*scale + bias terms) * w1, reduce over block columns
    #pragma unroll
    for (int mf = 0; mf < 4; mf++)
        #pragma unroll
        for (int rr = 0; rr < 2; rr++) {
            int lrow = wm * 64 + mf * 16 + (lane >> 2) + rr * 8;
            const __nv_bfloat16 *uA, *uB, *uF;
            if (EPI == 1) {
                uA = g_uabb + (size_t)sRi[lrow] * FFP;
                uB = g_uabb + (size_t)KTOP * FFP + (size_t)sRp[lrow] * FFP;
                uF = g_featb + (size_t)sRc[lrow] * FFP;
            } else {
                uA = g_Pb + (size_t)sRi[lrow] * FFP;
                uB = g_Pb + PSEC + (size_t)sRp[lrow] * FFP;
                uF = g_wmb + (size_t)sRc[lrow] * FFP;
            }
            float part = 0.f;
            #pragma unroll
            for (int nf = 0; nf < 4; nf++) {
                int f = col0 + wn * 32 + nf * 8 + (lane & 3) * 2;
                float2 va = __bfloat1622float2(*(const __nv_bfloat162*)(uA + f));
                float2 vb = __bfloat1622float2(*(const __nv_bfloat162*)(uB + f));
                float2 vf = __bfloat1622float2(*(const __nv_bfloat162*)(uF + f));
                #pragma unroll
                for (int c = 0; c < 2; c++) {
                    float v = acc[mf][nf][rr * 2 + c] * scale;
                    if (f + c < FFD) v += b0v[f + c];
                    v += (c ? va.y : va.x) + (c ? vb.y : vb.x) + (c ? vf.y : vf.x);
                    float w1f = (f + c < FFD) ? w1v[f + c] : 0.f;
                    part += fmaxf(v, 0.f) * w1f;
                }
            }
            atomicAdd(&rowsum[lrow], part);
        }
    __syncthreads();
    if (tid < BM) {
        int r = row0 + tid;
        if (r < R) g_part[(size_t)r * NCB + blockIdx.x] = rowsum[tid];
    }
}

// thin wrappers
template<int EPI, int FP8, int OUT16>
__global__ __launch_bounds__(256, 2) void hgemm2(
    const __nv_bfloat16* __restrict__ A, int lda,
    const __nv_bfloat16* __restrict__ Bg, int ldb, size_t bzStride,
    const float* __restrict__ b0v, const float* __restrict__ w1v,
    void* __restrict__ outCv, size_t czStride, int ldc,
    int kIter, int R, int maxC, float scale)
{
    extern __shared__ char smem[];
    if (EPI == 2) {
        Bg += blockIdx.z * bzStride;
        if (OUT16) outCv = (__nv_bfloat16*)outCv + blockIdx.z * czStride;
        else       outCv = (float*)outCv + blockIdx.z * czStride;
    }
    gemm_body<EPI, FP8, OUT16>(A, lda, Bg, ldb, b0v, w1v, outCv, ldc, kIter, R, maxC, scale, smem);
}

// fused src (z=0, bf16) + UA/UB (z=1,2, fp8) GEMM
__global__ __launch_bounds__(256, 2) void src_uab(
    const __nv_bfloat16* __restrict__ topbh, const __nv_bfloat16* __restrict__ topb8v,
    const __nv_bfloat16* __restrict__ c2h, const __nv_bfloat16* __restrict__ aw08v,
    const float* __restrict__ c2b, void* __restrict__ srch, void* __restrict__ uabb)
{
    extern __shared__ char smem[];
    int z = blockIdx.z;
    if (z == 0) {
        if (blockIdx.x >= C2N / BN) return;
        gemm_body<2, 0, 1>(topbh, KPAD, c2h, C2N, c2b, nullptr,
                           srch, KPAD, KPAD / BKK, KTOP, MD, 1.f, smem);
    } else {
        gemm_body<2, 1, 1>(topb8v, K16, aw08v + (size_t)(z - 1) * K16 * FFP, FFP,
                           nullptr, nullptr,
                           (__nv_bfloat16*)uabb + (size_t)(z - 1) * KTOP * FFP, FFP,
                           K16 / BKK, KTOP, FFP, 1.f / 512.f, smem);
    }
}

// ---------------- top-K mentions (folded mention reduce, warp-cooperative) ----------------
__global__ void topk_mentions(const int* __restrict__ spk, const int* __restrict__ sent,
                              const float* __restrict__ mb1, const float* __restrict__ wb1)
{
    extern __shared__ unsigned long long skeys[];   // NSP keys (64 KB)
    __shared__ int hist[256];
    __shared__ int tix[256];
    __shared__ unsigned long long s_pfx;
    __shared__ int s_tgt, s_cnt;
    int tid = threadIdx.x;            // 1024
    int lane = tid & 31, warp = tid >> 5;   // 32 warps
    float base = mb1[0] + wb1[0];
    // warp-cooperative reduce: one row per warp, lane<NCB reads one partial
    for (int i = warp; i < NSP; i += 32) {
        float part = (lane < NCB) ? g_part[(size_t)i * NCB + lane] : 0.f;
        #pragma unroll
        for (int o = 16; o > 0; o >>= 1) part += __shfl_down_sync(0xffffffffu, part, o);
        if (lane == 0) {
            int w = g_w[i] - 1;
            float m = base + part;
            #pragma unroll
            for (int c = 0; c < 6; c++) m += g_wpart[w * 6 + c];
            g_m[i] = m;
            skeys[i] = make_key(m, (unsigned)i);
        }
    }
    if (tid == 0) { s_tgt = KTOP; s_pfx = 0ull; s_cnt = 0; }
    __syncthreads();

    for (int byte = 7; byte >= 0; byte--) {
        int shift = byte * 8;
        if (tid < 256) hist[tid] = 0;
        __syncthreads();
        unsigned long long pfx = s_pfx;
        for (int i = tid; i < NSP; i += 1024) {
            unsigned long long k = skeys[i];
            bool match = (byte == 7) || ((k >> (shift + 8)) == (pfx >> (shift + 8)));
            if (match) atomicAdd(&hist[(int)((k >> shift) & 255)], 1);
        }
        __syncthreads();
        if (tid == 0) {
            int cum = 0, v = 255;
            for (; v > 0; v--) { if (cum + hist[v] >= s_tgt) break; cum += hist[v]; }
            s_tgt -= cum;
            s_pfx = pfx | ((unsigned long long)(unsigned)v << shift);
        }
        __syncthreads();
    }
    unsigned long long thr = s_pfx;
    for (int i = tid; i < NSP; i += 1024) {
        if (skeys[i] >= thr) {
            int pos = atomicAdd(&s_cnt, 1);
            if (pos < 256) tix[pos] = key_idx(skeys[i]);
        }
    }
    __syncthreads();
    for (int t = tid; t < 256; t += 1024) if (t >= KTOP) tix[t] = 0x7FFFFFFF;
    __syncthreads();
    for (unsigned k = 2; k <= 256; k <<= 1)
        for (unsigned j = k >> 1; j > 0; j >>= 1) {
            for (unsigned t = tid; t < 256; t += 1024) {
                unsigned ixj = t ^ j;
                if (ixj > t) {
                    int a = tix[t], b = tix[ixj];
                    bool asc = ((t & k) == 0);
                    if (asc ? (a > b) : (a < b)) { tix[t] = b; tix[ixj] = a; }
                }
            }
            __syncthreads();
        }
    if (tid < KTOP) {
        int idx = tix[tid];
        g_topidx[tid] = idx;
        g_topm[tid]   = g_m[idx];
        int s = g_s[idx];
        g_topspk[tid] = spk[s];
        g_topseg[tid] = sent[s];
    }
}

// ---------------- build top-204 base rows (bf16 + fp8 x8) ----------------
__global__ void build_topbase(const float* __restrict__ h, const float* __restrict__ width_emb)
{
    int i = blockIdx.x;               // KTOP blocks
    int tid = threadIdx.x;            // 256
    __shared__ float wts[32];
    __shared__ int shr[3];
    if (tid == 0) {
        int idx = g_topidx[i];
        shr[0] = g_s[idx]; shr[1] = g_e[idx]; shr[2] = g_w[idx];
    }
    __syncthreads();
    int s = shr[0], e = shr[1], w = shr[2];
    if (tid < 32) wts[tid] = g_wts[(size_t)g_topidx[i] * 32 + tid];
    __syncthreads();

    __nv_bfloat16* dsh = g_topbaseh + (size_t)i * KPAD;
    uint8_t* d8 = (uint8_t*)g_topb8 + (size_t)i * KPAD;
    const float* hs = h + (size_t)s * HD;
    const float* he = h + (size_t)e * HD;
    for (int c = tid; c < HD; c += 256) {
        float acc = 0.f;
        for (int wp = 0; wp < w; wp++) acc += wts[wp] * h[(size_t)(s + wp) * HD + c];
        float v0 = hs[c], v1 = he[c];
        dsh[c]          = __float2bfloat16(v0);
        dsh[HD + c]     = __float2bfloat16(v1);
        dsh[2 * HD + c] = __float2bfloat16(acc);
        d8[c]          = (uint8_t)(cvt_e4m3x2(v0 * 8.f, 0.f) & 0xFF);
        d8[HD + c]     = (uint8_t)(cvt_e4m3x2(v1 * 8.f, 0.f) & 0xFF);
        d8[2 * HD + c] = (uint8_t)(cvt_e4m3x2(acc * 8.f, 0.f) & 0xFF);
    }
    if (tid < 20) {
        float v = width_emb[(w - 1) * 20 + tid];
        dsh[3 * HD + tid] = __float2bfloat16(v);
        d8[3 * HD + tid]  = (uint8_t)(cvt_e4m3x2(v * 8.f, 0.f) & 0xFF);
    }
}

// ---------------- per-row top-C antecedents ----------------
__global__ void topc()
{
    int i = blockIdx.x;
    int tid = threadIdx.x;            // 128
    __shared__ unsigned long long keys[256];
    for (int t = tid; t < 256; t += 128)
        keys[t] = (t < KTOP) ? make_key(g_cp[i * KTOP + t], (unsigned)t) : 0ull;
    __syncthreads();
    for (unsigned k = 2; k <= 256; k <<= 1)
        for (unsigned j = k >> 1; j > 0; j >>= 1) {
            for (unsigned t = tid; t < 256; t += 128) {
                unsigned ixj = t ^ j;
                if (ixj > t) {
                    unsigned long long a = keys[t], b = keys[ixj];
                    bool desc = ((t & k) == 0);
                    if (desc ? (a < b) : (a > b)) { keys[t] = b; keys[ixj] = a; }
                }
            }
            __syncthreads();
        }
    if (tid < CANT) {
        int pos = key_idx(keys[tid]);
        g_antpos[i * CANT + tid] = pos;
        g_antsc[i * CANT + tid] = g_cp[i * KTOP + pos];
    }
}

// ---------------- compact pairwise product rows (fp8) ----------------
__global__ void pack_prod()
{
    int r = blockIdx.x;               // VPAD
    int tid = threadIdx.x;            // 256
    int i, c;
    pair_decode(r, i, c);
    int p = g_antpos[i * CANT + c];
    const uint4* a = (const uint4*)(g_topbaseh + (size_t)i * KPAD);
    const uint4* b = (const uint4*)(g_topbaseh + (size_t)p * KPAD);
    uint16_t* o = g_pair8 + (size_t)r * K16;
    for (int v = tid; v < KPAD / 8; v += 256) {
        uint4 va = a[v], vb = b[v];
        __nv_bfloat162* pa = (__nv_bfloat162*)&va;
        __nv_bfloat162* pb = (__nv_bfloat162*)&vb;
        uint16_t res[4];
        #pragma unroll
        for (int q = 0; q < 4; q++) {
            float2 fa = __bfloat1622float2(pa[q]);
            float2 fb = __bfloat1622float2(pb[q]);
            res[q] = cvt_e4m3x2(fa.x * fb.x, fa.y * fb.y);
        }
        *(uint64_t*)(o + v * 4) = *(uint64_t*)res;
    }
}

// ---------------- final output (folded fine reduce) ----------------
__global__ void final_out(float* __restrict__ out, const float* __restrict__ dummy,
                          const float* __restrict__ ab1)
{
    int i = blockIdx.x;
    int tid = threadIdx.x;            // 64
    if (tid == 0) out[i * (CANT + 1)] = dummy[0];
    if (tid < CANT) {
        int nvalid = (i < CANT) ? i : CANT;
        bool valid = tid < nvalid;
        float v = NEG9;
        if (valid) {
            int r = pair_off(i) + tid;
            float fine = ab1[0];
            #pragma unroll
            for (int c = 0; c < NCB; c++) fine += g_part[(size_t)r * NCB + c];
            v = g_antsc[i * CANT + tid] + fine * 2.0f;
        }
        out[i * (CANT + 1) + 1 + tid] = v;
    }
}

// ---------------- launch ----------------
extern "C" void kernel_launch(void* const* d_in, const int* in_sizes, int n_in,
                              void* d_out, int out_size)
{
    const float* h          = (const float*)d_in[0];
    const int*   spans      = (const int*)  d_in[1];
    const int*   spk_ids    = (const int*)  d_in[2];
    const int*   gen_ids    = (const int*)  d_in[3];
    const int*   sent_map   = (const int*)  d_in[4];
    const float* w_head     = (const float*)d_in[5];
    const float* b_head     = (const float*)d_in[6];
    const float* width_emb  = (const float*)d_in[7];
    const float* width_prior= (const float*)d_in[8];
    const float* speaker_emb= (const float*)d_in[9];
    const float* segment_emb= (const float*)d_in[10];
    const float* genre_emb  = (const float*)d_in[11];
    const float* dist_emb   = (const float*)d_in[12];
    const float* mention_w0 = (const float*)d_in[13];
    const float* mention_b0 = (const float*)d_in[14];
    const float* mention_w1 = (const float*)d_in[15];
    const float* mention_b1 = (const float*)d_in[16];
    const float* width_w0   = (const float*)d_in[17];
    const float* width_b0   = (const float*)d_in[18];
    const float* width_w1   = (const float*)d_in[19];
    const float* width_b1   = (const float*)d_in[20];
    const float* c2_w       = (const float*)d_in[21];
    const float* c2_b       = (const float*)d_in[22];
    const float* ant_w0     = (const float*)d_in[23];
    const float* ant_b0     = (const float*)d_in[24];
    const float* ant_w1     = (const float*)d_in[25];
    const float* ant_b1     = (const float*)d_in[26];
    const float* dummy_bias = (const float*)d_in[27];
    float* out = (float*)d_out;

    cudaFuncSetAttribute((const void*)hgemm2<1,1,0>, cudaFuncAttributeMaxDynamicSharedMemorySize, DSMEM_ALL);
    cudaFuncSetAttribute((const void*)hgemm2<2,0,1>, cudaFuncAttributeMaxDynamicSharedMemorySize, DSMEM_ALL);
    cudaFuncSetAttribute((const void*)hgemm2<3,1,0>, cudaFuncAttributeMaxDynamicSharedMemorySize, DSMEM_ALL);
    cudaFuncSetAttribute((const void*)hgemm2<4,0,0>, cudaFuncAttributeMaxDynamicSharedMemorySize, DSMEM_ALL);
    cudaFuncSetAttribute((const void*)src_uab, cudaFuncAttributeMaxDynamicSharedMemorySize, DSMEM_ALL);
    cudaFuncSetAttribute(topk_mentions, cudaFuncAttributeMaxDynamicSharedMemorySize, NSP * 8);

    void *pW0h, *pAw08, *pC2h, *pPair8, *pTopbh, *pTopb8, *pUabb, *pHh, *pSw8, *pPh8, *pPb;
    void *pSrch, *pTopbT, *pCp;
    cudaGetSymbolAddress(&pW0h,   g_w0h);
    cudaGetSymbolAddress(&pAw08,  g_aw08);
    cudaGetSymbolAddress(&pC2h,   g_c2h);
    cudaGetSymbolAddress(&pPair8, g_pair8);
    cudaGetSymbolAddress(&pTopbh, g_topbaseh);
    cudaGetSymbolAddress(&pTopb8, g_topb8);
    cudaGetSymbolAddress(&pUabb,  g_uabb);
    cudaGetSymbolAddress(&pHh,    g_hh);
    cudaGetSymbolAddress(&pSw8,   g_sw8);
    cudaGetSymbolAddress(&pPh8,   g_ph8);
    cudaGetSymbolAddress(&pPb,    g_Pb);
    cudaGetSymbolAddress(&pSrch,  g_srch);
    cudaGetSymbolAddress(&pTopbT, g_topbT);
    cudaGetSymbolAddress(&pCp,    g_cp);
    const __nv_bfloat16* aw08  = (const __nv_bfloat16*)pAw08;   // b16 view of fp8 pairs
    const __nv_bfloat16* c2h   = (const __nv_bfloat16*)pC2h;
    const __nv_bfloat16* pair8 = (const __nv_bfloat16*)pPair8;  // b16 view
    const __nv_bfloat16* topbh = (const __nv_bfloat16*)pTopbh;
    const __nv_bfloat16* topb8 = (const __nv_bfloat16*)pTopb8;  // b16 view
    const __nv_bfloat16* hh    = (const __nv_bfloat16*)pHh;
    const __nv_bfloat16* sw8   = (const __nv_bfloat16*)pSw8;    // b16 view
    const __nv_bfloat16* ph8   = (const __nv_bfloat16*)pPh8;    // b16 view
    const __nv_bfloat16* srch  = (const __nv_bfloat16*)pSrch;
    const __nv_bfloat16* topbT = (const __nv_bfloat16*)pTopbT;
    const __nv_bfloat16* w0h   = (const __nv_bfloat16*)pW0h;

    // 1) conversions + wproj + width_scores + tok_score + featcomb, one launch
    mega_prep<<<S7E, 256>>>(mention_w0, ant_w0, c2_w, h, w_head, b_head,
                            width_emb, width_prior, width_w0, width_b0, width_w1,
                            speaker_emb, genre_emb, dist_emb, segment_emb, gen_ids);

    // 2) span softmax weights
    span_prep<<<NSP / 8, 256>>>(spans);

    // 3) P_s | P_e | P_h = h @ W0 sections -> bf16  (M=512, K=768)
    hgemm2<2,0,1><<<dim3(NCB, LEN / BM, 3), 256, DSMEM_ALL>>>(
        hh, HD, w0h, FFP, (size_t)HD * FFP, nullptr, nullptr,
        pPb, PSEC, FFP, HD / BKK, LEN, FFP, 1.f);
    conv_ph8<<<dim3(FFP / 256, SW16), 256>>>();

    // 4) mention MLP: SW(fp8) @ P_h(fp8), epilogue adds Pb_s[s]+Pb_e[e]+wmb[w-1]
    hgemm2<3,1,0><<<dim3(NCB, NSP / BM), 256, DSMEM_ALL>>>(
        sw8, SW16, ph8, FFP, 0, mention_b0, mention_w1,
        nullptr, 0, 0, SW16 / BKK, NSP, FFP, 1.f / 4096.f);

    // 5) top-K (with folded, warp-cooperative mention reduce) + top-base rebuild
    topk_mentions<<<1, 1024, NSP * 8>>>(spk_ids, sent_map, mention_b1, width_b1);
    build_topbase<<<KTOP, 256>>>(h, width_emb);
    transp_topb<<<dim3(KPAD / 32, 8), dim3(32, 8)>>>();

    // 6) fused: src = top_base @ c2_w + c2_b (bf16), UA/UB = top_base @ W0a/b (fp8)
    src_uab<<<dim3(NCB, 2, 3), 256, DSMEM_ALL>>>(
        topbh, topb8, c2h, aw08, c2_b, pSrch, pUabb);

    // 7) cp = src @ top_base^T + topm_i + topm_j, tril mask
    hgemm2<4,0,0><<<dim3(2, 2, 1), 256, DSMEM_ALL>>>(
        srch, KPAD, topbT, 256, 0, nullptr, nullptr,
        pCp, 0, KTOP, KPAD / BKK, KTOP, KTOP, 1.f);

    topc<<<KTOP, 128>>>();
    pack_prod<<<VPAD, 256>>>();

    // 8) fine pairwise MLP (fp8, compact valid rows), scale 1/64
    hgemm2<1,1,0><<<dim3(NCB, VPAD / BM), 256, DSMEM_ALL>>>(
        pair8, K16, aw08 + 2 * (size_t)K16 * FFP, FFP, 0, ant_b0, ant_w1,
        nullptr, 0, 0, K16 / BKK, VPAD, FFP, 1.f / 64.f);

    // 9) output (with folded fine reduce)
    final_out<<<KTOP, 64>>>(out, dummy_bias, ant_b1);
}

// round 15
// speedup vs baseline: 1.3544x; 1.3544x over previous
#include <cuda_runtime.h>
#include <cuda_bf16.h>
#include <math.h>
#include <stdint.h>

#define NSP   8192
#define LEN   512
#define HD    768
#define MAXW  30
#define FFD   3000
#define MD    2324      // 3*768+20
#define KTOP  204
#define CANT  50
#define NEG9  (-1e9f)

#define TRI   1225      // 50*49/2
#define VROWS 8925      // valid pairs: sum min(i,50)
#define VPAD  8960      // 70 * 128

#define KPAD  2368      // MD padded to multiple of 64
#define K16   1184      // KPAD/2 : b16 units per fp8 row
#define SW16  256       // LEN/2  : b16 units per fp8 SW row
#define FFP   3072      // FFD padded to multiple of 128
#define C2N   2432      // MD padded to multiple of 128 (src gemm N)
#define NCB   24        // FFP/128
#define BM    128
#define BN    128
#define BKK   32
#define PSEC  ((size_t)LEN * FFP)

#define STAGES 4
#define A_PITCH 40
#define B_PITCH 136
#define A_BYTES (BM * A_PITCH * 2)        // 10240
#define B_BYTES (BKK * B_PITCH * 2)       // 8704
#define STAGE_BYTES (A_BYTES + B_BYTES)   // 18944
#define DSMEM (STAGES * STAGE_BYTES)      // 75776
#define DSMEM_ALL (DSMEM + 128 * 16)      // + rowsum/sRi/sRp/sRc tail = 77824

// mega_prep section boundaries (linear block index)
#define S0E 7104     // conv_w0   : d(2368) x f4grp(3)
#define S1E 49728    // conv_aw08 : sec(3) x k16(1184) x ngrp(12)
#define S2E 56832    // conv_c2   : d(2368) x f4grp(3)
#define S3E 57216    // conv_h    : 384
#define S4E 57246    // wproj     : 30
#define S5E 57426    // width_scores : 30 x 6
#define S6E 57490    // tok_score : 64 (8 tokens/block)

// ---------------- scratch (static device globals; zero-initialized) ----------------
__device__ __nv_bfloat16  g_w0h[(size_t)KPAD * FFP];       // mention_w0 bf16
__device__ uint16_t       g_aw08[3 * (size_t)K16 * FFP];   // ant_w0 a,b,c fp8 pair-interleaved x64
__device__ __nv_bfloat16  g_c2h[(size_t)KPAD * C2N];       // c2_w bf16 padded
__device__ uint16_t       g_pair8[(size_t)VPAD * K16];     // compact pair products, fp8 (pad rows stay 0)
__device__ __nv_bfloat16  g_hh[(size_t)LEN * HD];          // h bf16
__device__ uint8_t        g_sw8[(size_t)NSP * LEN];        // span softmax weights fp8 x64
__device__ __nv_bfloat16  g_Pb[3 * PSEC];                  // P_s | P_e | P_h  (bf16)
__device__ uint16_t       g_ph8[(size_t)SW16 * FFP];       // P_h fp8 pair-interleaved x64
__device__ __nv_bfloat16  g_srch[(size_t)256 * KPAD];      // src bf16 (padding stays 0)
__device__ __nv_bfloat16  g_topbT[(size_t)KPAD * 256];     // top_base^T bf16
__device__ __nv_bfloat16  g_wmb[MAXW * FFP];               // width_emb @ W0_w (bf16)
__device__ float g_tok[LEN];
__device__ float g_wts[(size_t)NSP * 32];                  // fp32 softmax weights
__device__ int   g_w[NSP];
__device__ int   g_s[NSP];
__device__ int   g_e[NSP];
__device__ float g_m[NSP];
__device__ float g_wpart[MAXW * 6];
__device__ int   g_topidx[KTOP];
__device__ float g_topm[KTOP];
__device__ int   g_topspk[KTOP];
__device__ int   g_topseg[KTOP];
__device__ __nv_bfloat16 g_topbaseh[(size_t)256 * KPAD];   // rows 204..255 stay 0
__device__ uint16_t      g_topb8[(size_t)256 * K16];       // top_base fp8 x8 (rows 204..255 zero)
__device__ float g_cp[KTOP * KTOP];
__device__ float g_antsc[KTOP * CANT];
__device__ int   g_antpos[KTOP * CANT];
__device__ __nv_bfloat16 g_uabb[2 * (size_t)KTOP * FFP];   // UA | UB (bf16)
__device__ float g_ftab[22 * FFP];
__device__ __nv_bfloat16 g_featb[60 * FFP];                // combined feature rows (bf16)
__device__ float g_fine[VPAD];
__device__ float g_part[(size_t)NSP * NCB];

// orderable key: primary = value descending, secondary = index ascending
__device__ __forceinline__ unsigned long long make_key(float v, unsigned idx) {
    unsigned u = __float_as_uint(v);
    u = (u & 0x80000000u) ? ~u : (u | 0x80000000u);
    return ((unsigned long long)u << 32) | (unsigned)(0xFFFFFFFFu - idx);
}
__device__ __forceinline__ int key_idx(unsigned long long k) {
    return (int)(0xFFFFFFFFu - (unsigned)(k & 0xFFFFFFFFu));
}

// compact pair index t -> (i, c) with c < min(i, CANT)
__device__ __forceinline__ void pair_decode(int t, int& i, int& c) {
    if (t < TRI) {
        int ii = (int)((sqrtf(8.f * t + 1.f) + 1.f) * 0.5f);
        while (ii * (ii - 1) / 2 > t) ii--;
        while ((ii + 1) * ii / 2 <= t) ii++;
        i = ii; c = t - ii * (ii - 1) / 2;
    } else {
        int u = t - TRI;
        i = 50 + u / 50; c = u % 50;
        if (i > KTOP - 1) { i = KTOP - 1; c = CANT - 1; }
    }
}
__device__ __forceinline__ int pair_off(int i) {
    return (i <= 50) ? i * (i - 1) / 2 : TRI + (i - 50) * 50;
}

// ---------------- PTX helpers ----------------
__device__ __forceinline__ void cp_async16(void* s, const void* g) {
    uint32_t sa = (uint32_t)__cvta_generic_to_shared(s);
    asm volatile("cp.async.cg.shared.global [%0], [%1], 16;" :: "r"(sa), "l"(g));
}
__device__ __forceinline__ void cp_commit() { asm volatile("cp.async.commit_group;"); }
template<int N> __device__ __forceinline__ void cp_wait() {
    asm volatile("cp.async.wait_group %0;" :: "n"(N));
}
__device__ __forceinline__ void ldsm_x4(uint32_t* r, uint32_t addr) {
    asm volatile("ldmatrix.sync.aligned.m8n8.x4.shared.b16 {%0,%1,%2,%3}, [%4];"
                 : "=r"(r[0]), "=r"(r[1]), "=r"(r[2]), "=r"(r[3]) : "r"(addr));
}
__device__ __forceinline__ void ldsm_x4_t(uint32_t* r, uint32_t addr) {
    asm volatile("ldmatrix.sync.aligned.m8n8.x4.trans.shared.b16 {%0,%1,%2,%3}, [%4];"
                 : "=r"(r[0]), "=r"(r[1]), "=r"(r[2]), "=r"(r[3]) : "r"(addr));
}
__device__ __forceinline__ void mma_bf16(float* c, const uint32_t* a, uint32_t b0, uint32_t b1) {
    asm volatile("mma.sync.aligned.m16n8k16.row.col.f32.bf16.bf16.f32 "
                 "{%0,%1,%2,%3}, {%4,%5,%6,%7}, {%8,%9}, {%0,%1,%2,%3};"
                 : "+f"(c[0]), "+f"(c[1]), "+f"(c[2]), "+f"(c[3])
                 : "r"(a[0]), "r"(a[1]), "r"(a[2]), "r"(a[3]), "r"(b0), "r"(b1));
}
__device__ __forceinline__ void mma_fp8(float* c, const uint32_t* a, uint32_t b0, uint32_t b1) {
    asm volatile("mma.sync.aligned.m16n8k32.row.col.f32.e4m3.e4m3.f32 "
                 "{%0,%1,%2,%3}, {%4,%5,%6,%7}, {%8,%9}, {%0,%1,%2,%3};"
                 : "+f"(c[0]), "+f"(c[1]), "+f"(c[2]), "+f"(c[3])
                 : "r"(a[0]), "r"(a[1]), "r"(a[2]), "r"(a[3]), "r"(b0), "r"(b1));
}
// pack two floats into e4m3x2: low byte = lo, high byte = hi
__device__ __forceinline__ uint16_t cvt_e4m3x2(float lo, float hi) {
    uint16_t d;
    asm("cvt.rn.satfinite.e4m3x2.f32 %0, %1, %2;" : "=h"(d) : "f"(hi), "f"(lo));
    return d;
}

// ---------------- mega prep: all conversions + wproj + width_scores + tok_score ----------------
__global__ void mega_prep(const float* __restrict__ mention_w0, const float* __restrict__ ant_w0,
                          const float* __restrict__ c2w, const float* __restrict__ h,
                          const float* __restrict__ w_head, const float* __restrict__ b_head,
                          const float* __restrict__ width_emb, const float* __restrict__ wprior,
                          const float* __restrict__ ww0, const float* __restrict__ wb0,
                          const float* __restrict__ ww1)
{
    __shared__ float shA[256];
    __shared__ float shB[32];
    int b = blockIdx.x;
    int tid = threadIdx.x;

    if (b < S0E) {                         // conv_w0 (bf16)
        int d = b / 3, fx = b % 3;
        int f4 = fx * 256 + tid;
        if (f4 >= FFP / 4) return;
        float4 v = make_float4(0.f, 0.f, 0.f, 0.f);
        if (d < MD && f4 < FFD / 4)
            v = *(const float4*)(mention_w0 + (size_t)d * FFD + f4 * 4);
        __nv_bfloat16 o[4] = { __float2bfloat16(v.x), __float2bfloat16(v.y),
                               __float2bfloat16(v.z), __float2bfloat16(v.w) };
        *(uint64_t*)(g_w0h + (size_t)d * FFP + f4 * 4) = *(uint64_t*)o;
    } else if (b < S1E) {                  // conv_aw08 (fp8 x64 pair-interleaved)
        int id = b - S0E;
        int s = id / (12 * K16);
        int rem = id % (12 * K16);
        int k16 = rem / 12, nx = rem % 12;
        int n = nx * 256 + tid;
        if (n >= FFP) return;
        int k0 = 2 * k16, k1 = 2 * k16 + 1;
        float lo = 0.f, hi = 0.f;
        if (n < FFD) {
            if (k0 < MD) lo = ant_w0[(size_t)(s * MD + k0) * FFD + n] * 64.f;
            if (k1 < MD) hi = ant_w0[(size_t)(s * MD + k1) * FFD + n] * 64.f;
        }
        g_aw08[(size_t)s * K16 * FFP + (size_t)k16 * FFP + n] = cvt_e4m3x2(lo, hi);
    } else if (b < S2E) {                  // conv_c2 (bf16)
        int id = b - S1E;
        int d = id / 3, fx = id % 3;
        int f4 = fx * 256 + tid;
        if (f4 >= C2N / 4) return;
        float4 v = make_float4(0.f, 0.f, 0.f, 0.f);
        if (d < MD) {
            float t[4];
            #pragma unroll
            for (int q = 0; q < 4; q++)
                t[q] = (f4 * 4 + q < MD) ? c2w[(size_t)d * MD + f4 * 4 + q] : 0.f;
            v = make_float4(t[0], t[1], t[2], t[3]);
        }
        __nv_bfloat16 o[4] = { __float2bfloat16(v.x), __float2bfloat16(v.y),
                               __float2bfloat16(v.z), __float2bfloat16(v.w) };
        *(uint64_t*)(g_c2h + (size_t)d * C2N + f4 * 4) = *(uint64_t*)o;
    } else if (b < S3E) {                  // conv_h (bf16)
        size_t i4 = (size_t)(b - S2E) * 256 + tid;
        if (i4 >= (size_t)LEN * HD / 4) return;
        float4 v = *(const float4*)(h + i4 * 4);
        __nv_bfloat16 o[4] = { __float2bfloat16(v.x), __float2bfloat16(v.y),
                               __float2bfloat16(v.z), __float2bfloat16(v.w) };
        *(uint64_t*)(g_hh + i4 * 4) = *(uint64_t*)o;
    } else if (b < S4E) {                  // wproj -> g_wmb (bf16)
        int w = b - S3E;
        if (tid < 20) shB[tid] = width_emb[w * 20 + tid];
        __syncthreads();
        for (int f = tid; f < FFP; f += 256) {
            float acc = 0.f;
            if (f < FFD) {
                #pragma unroll
                for (int k = 0; k < 20; k++)
                    acc += shB[k] * mention_w0[(size_t)(3 * HD + k) * FFD + f];
            }
            g_wmb[(size_t)w * FFP + f] = __float2bfloat16(acc);
        }
    } else if (b < S5E) {                  // width_scores -> g_wpart
        int id = b - S4E;
        int w = id / 6, seg = id % 6;
        if (tid < 20) shB[tid] = wprior[w * 20 + tid];
        __syncthreads();
        float acc = 0.f;
        int f0 = seg * 512;
        int f1 = min(f0 + 512, FFD);
        for (int f = f0 + tid; f < f1; f += 256) {
            float d = wb0[f];
            #pragma unroll
            for (int k = 0; k < 20; k++) d += shB[k] * ww0[k * FFD + f];
            acc += fmaxf(d, 0.f) * ww1[f];
        }
        shA[tid] = acc;
        __syncthreads();
        for (int o = 128; o > 0; o >>= 1) { if (tid < o) shA[tid] += shA[tid + o]; __syncthreads(); }
        if (tid == 0) g_wpart[w * 6 + seg] = shA[0];
    } else if (b < S6E) {                  // tok_score (8 tokens per block)
        int t = (b - S5E) * 8 + (tid >> 5);
        int lane = tid & 31;
        if (t >= LEN) return;
        const float* row = h + (size_t)t * HD;
        float acc = 0.f;
        for (int c = lane; c < HD; c += 32) acc += row[c] * w_head[c];
        #pragma unroll
        for (int o = 16; o > 0; o >>= 1) acc += __shfl_down_sync(0xffffffffu, acc, o);
        if (lane == 0) g_tok[t] = acc + b_head[0];
    }
}

// P_h (bf16 section 2 of g_Pb) -> fp8 pair-interleaved x64
__global__ void conv_ph8()
{
    int f = blockIdx.x * 256 + threadIdx.x;      // 0..FFP-1
    int k16 = blockIdx.y;                        // 0..SW16-1
    if (f >= FFP) return;
    float lo = __bfloat162float(g_Pb[2 * PSEC + (size_t)(2 * k16) * FFP + f]) * 64.f;
    float hi = __bfloat162float(g_Pb[2 * PSEC + (size_t)(2 * k16 + 1) * FFP + f]) * 64.f;
    g_ph8[(size_t)k16 * FFP + f] = cvt_e4m3x2(lo, hi);
}
__global__ void transp_topb()
{
    __shared__ __nv_bfloat16 t[32][33];
    int k0 = blockIdx.x * 32, j0 = blockIdx.y * 32;
    int tx = threadIdx.x, ty = threadIdx.y;   // (32, 8)
    #pragma unroll
    for (int r = 0; r < 4; r++)
        t[ty + r * 8][tx] = g_topbaseh[(size_t)(j0 + ty + r * 8) * KPAD + k0 + tx];
    __syncthreads();
    #pragma unroll
    for (int r = 0; r < 4; r++)
        g_topbT[(size_t)(k0 + ty + r * 8) * 256 + j0 + tx] = t[tx][ty + r * 8];
}

// ---------------- span softmax weights (fp8 x64 rows) ----------------
__global__ void span_prep(const int* __restrict__ spans)
{
    int n = blockIdx.x * 8 + (threadIdx.x >> 5);
    int lane = threadIdx.x & 31;
    if (n >= NSP) return;
    int s = spans[2 * n], e = spans[2 * n + 1];
    s = min(max(s, 0), LEN - 1);
    e = min(max(e, 0), LEN - 1);
    int w = e - s + 1;
    if (w < 1) w = 1;
    if (w > MAXW) w = MAXW;
    if (lane == 0) { g_s[n] = s; g_e[n] = e; g_w[n] = w; }
    float v = (lane < w) ? g_tok[s + lane] : -1e30f;
    float mx = v;
    #pragma unroll
    for (int o = 16; o > 0; o >>= 1) mx = fmaxf(mx, __shfl_xor_sync(0xffffffffu, mx, o));
    float p = (lane < w) ? expf(v - mx) : 0.f;
    float sm = p;
    #pragma unroll
    for (int o = 16; o > 0; o >>= 1) sm += __shfl_xor_sync(0xffffffffu, sm, o);
    float wt = p / sm;
    g_wts[(size_t)n * 32 + lane] = wt;
    if (lane < w) {
        uint16_t pk = cvt_e4m3x2(wt * 64.f, 0.f);
        g_sw8[(size_t)n * LEN + s + lane] = (uint8_t)(pk & 0xFF);
    }
}

// ---------------- tensor-core GEMM body (inlined; cp.async 4-stage) ----------------
// EPI 1: fused fine epilogue  (+ uabb[i] + uabb[K+p] + featb[code]) -> g_part
// EPI 2: raw C (*scale, +optional bias) -> outC (fp32 or bf16 per OUT16)
// EPI 3: fused mention epilogue (+ Pb_s[s] + Pb_e[e] + wmb[w-1])    -> g_part
// EPI 4: cp epilogue: + topm[r] + topm[f], tril mask -> g_cp (fp32)
template<int EPI, int FP8, int OUT16>
__device__ __forceinline__ void gemm_body(
    const __nv_bfloat16* __restrict__ A, int lda,
    const __nv_bfloat16* __restrict__ Bg, int ldb,
    const float* __restrict__ b0v, const float* __restrict__ w1v,
    void* __restrict__ outCv, int ldc,
    int kIter, int R, int maxC, float scale, char* smem)
{
    float* rowsum = (float*)(smem + DSMEM);
    int* sRi = (int*)(rowsum + 128);
    int* sRp = sRi + 128;
    int* sRc = sRp + 128;

    int tid = threadIdx.x;
    int lane = tid & 31, warp = tid >> 5;
    int wm = warp >> 2, wn = warp & 3;
    int row0 = blockIdx.y * BM, col0 = blockIdx.x * BN;

    if (tid < BM) {
        rowsum[tid] = 0.f;
        int r = row0 + tid;
        if (EPI == 1) {
            int i, c;
            pair_decode(r, i, c);
            int p = g_antpos[i * CANT + c];
            sRi[tid] = i; sRp[tid] = p;
            int same = (g_topspk[i] == g_topspk[p]) ? 1 : 0;
            int off = i - p; if (off < 0) off = 0;
            int bk = off >= 64 ? 9 : off >= 32 ? 8 : off >= 16 ? 7 : off >= 8 ? 6 : off >= 5 ? 5 : off;
            int ds = g_topseg[i] - g_topseg[p]; ds = ds < 0 ? 0 : (ds > 2 ? 2 : ds);
            sRc[tid] = (same * 10 + bk) * 3 + ds;
        }
        if (EPI == 3) {
            sRi[tid] = g_s[r]; sRp[tid] = g_e[r]; sRc[tid] = g_w[r] - 1;
        }
    }
    __syncthreads();

    float acc[4][4][4];
    #pragma unroll
    for (int a = 0; a < 4; a++)
        #pragma unroll
        for (int b = 0; b < 4; b++)
            #pragma unroll
            for (int c = 0; c < 4; c++) acc[a][b][c] = 0.f;

    auto issue = [&](int kt) {
        int k0 = kt * BKK;
        char* sa = smem + (size_t)(kt % STAGES) * STAGE_BYTES;
        char* sb = sa + A_BYTES;
        #pragma unroll
        for (int v = 0; v < 2; v++) {
            int idx = tid + v * 256;
            int arow = idx >> 2, aseg = idx & 3;
            cp_async16(sa + (size_t)(arow * A_PITCH + aseg * 8) * 2,
                       A + (size_t)(row0 + arow) * lda + k0 + aseg * 8);
            int brow = idx >> 4, bseg = idx & 15;
            cp_async16(sb + (size_t)(brow * B_PITCH + bseg * 8) * 2,
                       Bg + (size_t)(k0 + brow) * ldb + col0 + bseg * 8);
        }
    };

    #pragma unroll
    for (int s = 0; s < STAGES - 1; s++) { issue(s); cp_commit(); }

    for (int kt = 0; kt < kIter; kt++) {
        cp_wait<STAGES - 2>();
        __syncthreads();
        if (kt + STAGES - 1 < kIter) issue(kt + STAGES - 1);
        cp_commit();

        int cur = kt % STAGES;
        const __nv_bfloat16 (*As)[A_PITCH] =
            (const __nv_bfloat16 (*)[A_PITCH])(smem + (size_t)cur * STAGE_BYTES);
        const __nv_bfloat16 (*Bs)[B_PITCH] =
            (const __nv_bfloat16 (*)[B_PITCH])(smem + (size_t)cur * STAGE_BYTES + A_BYTES);

        #pragma unroll
        for (int kk = 0; kk < BKK; kk += 16) {
            uint32_t af[4][4];
            #pragma unroll
            for (int mf = 0; mf < 4; mf++) {
                uint32_t addr = (uint32_t)__cvta_generic_to_shared(
                    &As[wm * 64 + mf * 16 + (lane & 15)][kk + ((lane >> 4) << 3)]);
                ldsm_x4(af[mf], addr);
            }
            uint32_t bfr[2][4];
            #pragma unroll
            for (int g = 0; g < 2; g++) {
                int krow = kk + (lane & 7) + ((lane & 8) ? 8 : 0);
                int bcol = wn * 32 + g * 16 + ((lane & 16) ? 8 : 0);
                uint32_t addr = (uint32_t)__cvta_generic_to_shared(&Bs[krow][bcol]);
                ldsm_x4_t(bfr[g], addr);
            }
            #pragma unroll
            for (int mf = 0; mf < 4; mf++)
                #pragma unroll
                for (int nf = 0; nf < 4; nf++) {
                    if (FP8)
                        mma_fp8(acc[mf][nf], af[mf], bfr[nf >> 1][(nf & 1) * 2],
                                bfr[nf >> 1][(nf & 1) * 2 + 1]);
                    else
                        mma_bf16(acc[mf][nf], af[mf], bfr[nf >> 1][(nf & 1) * 2],
                                 bfr[nf >> 1][(nf & 1) * 2 + 1]);
                }
        }
        __syncthreads();
    }

    if (EPI == 2 || EPI == 4) {
        float* outF = (float*)outCv;
        __nv_bfloat16* outH = (__nv_bfloat16*)outCv;
        #pragma unroll
        for (int mf = 0; mf < 4; mf++)
            #pragma unroll
            for (int rr = 0; rr < 2; rr++) {
                int r = row0 + wm * 64 + mf * 16 + (lane >> 2) + rr * 8;
                if (r >= R) continue;
                #pragma unroll
                for (int nf = 0; nf < 4; nf++) {
                    int f = col0 + wn * 32 + nf * 8 + (lane & 3) * 2;
                    #pragma unroll
                    for (int c = 0; c < 2; c++) {
                        if (f + c < maxC) {
                            float v = acc[mf][nf][rr * 2 + c] * scale;
                            if (EPI == 4) {
                                v += g_topm[r] + g_topm[f + c];
                                if (f + c >= r) v = NEG9;
                            } else if (b0v) v += b0v[f + c];
                            if (OUT16) outH[(size_t)r * ldc + f + c] = __float2bfloat16(v);
                            else       outF[(size_t)r * ldc + f + c] = v;
                        }
                    }
                }
            }
        return;
    }

    // fused epilogue: relu(acc*scale + bias terms) * w1, reduce over block columns
    #pragma unroll
    for (int mf = 0; mf < 4; mf++)
        #pragma unroll
        for (int rr = 0; rr < 2; rr++) {
            int lrow = wm * 64 + mf * 16 + (lane >> 2) + rr * 8;
            const __nv_bfloat16 *uA, *uB, *uF;
            if (EPI == 1) {
                uA = g_uabb + (size_t)sRi[lrow] * FFP;
                uB = g_uabb + (size_t)KTOP * FFP + (size_t)sRp[lrow] * FFP;
                uF = g_featb + (size_t)sRc[lrow] * FFP;
            } else {
                uA = g_Pb + (size_t)sRi[lrow] * FFP;
                uB = g_Pb + PSEC + (size_t)sRp[lrow] * FFP;
                uF = g_wmb + (size_t)sRc[lrow] * FFP;
            }
            float part = 0.f;
            #pragma unroll
            for (int nf = 0; nf < 4; nf++) {
                int f = col0 + wn * 32 + nf * 8 + (lane & 3) * 2;
                float2 va = __bfloat1622float2(*(const __nv_bfloat162*)(uA + f));
                float2 vb = __bfloat1622float2(*(const __nv_bfloat162*)(uB + f));
                float2 vf = __bfloat1622float2(*(const __nv_bfloat162*)(uF + f));
                #pragma unroll
                for (int c = 0; c < 2; c++) {
                    float v = acc[mf][nf][rr * 2 + c] * scale;
                    if (f + c < FFD) v += b0v[f + c];
                    v += (c ? va.y : va.x) + (c ? vb.y : vb.x) + (c ? vf.y : vf.x);
                    float w1f = (f + c < FFD) ? w1v[f + c] : 0.f;
                    part += fmaxf(v, 0.f) * w1f;
                }
            }
            atomicAdd(&rowsum[lrow], part);
        }
    __syncthreads();
    if (tid < BM) {
        int r = row0 + tid;
        if (r < R) g_part[(size_t)r * NCB + blockIdx.x] = rowsum[tid];
    }
}

// thin wrappers
template<int EPI, int FP8, int OUT16>
__global__ __launch_bounds__(256, 2) void hgemm2(
    const __nv_bfloat16* __restrict__ A, int lda,
    const __nv_bfloat16* __restrict__ Bg, int ldb, size_t bzStride,
    const float* __restrict__ b0v, const float* __restrict__ w1v,
    void* __restrict__ outCv, size_t czStride, int ldc,
    int kIter, int R, int maxC, float scale)
{
    extern __shared__ char smem[];
    if (EPI == 2) {
        Bg += blockIdx.z * bzStride;
        if (OUT16) outCv = (__nv_bfloat16*)outCv + blockIdx.z * czStride;
        else       outCv = (float*)outCv + blockIdx.z * czStride;
    }
    gemm_body<EPI, FP8, OUT16>(A, lda, Bg, ldb, b0v, w1v, outCv, ldc, kIter, R, maxC, scale, smem);
}

// fused src (z=0, bf16) + UA/UB (z=1,2, fp8) GEMM
__global__ __launch_bounds__(256, 2) void src_uab(
    const __nv_bfloat16* __restrict__ topbh, const __nv_bfloat16* __restrict__ topb8v,
    const __nv_bfloat16* __restrict__ c2h, const __nv_bfloat16* __restrict__ aw08v,
    const float* __restrict__ c2b, void* __restrict__ srch, void* __restrict__ uabb)
{
    extern __shared__ char smem[];
    int z = blockIdx.z;
    if (z == 0) {
        if (blockIdx.x >= C2N / BN) return;
        gemm_body<2, 0, 1>(topbh, KPAD, c2h, C2N, c2b, nullptr,
                           srch, KPAD, KPAD / BKK, KTOP, MD, 1.f, smem);
    } else {
        gemm_body<2, 1, 1>(topb8v, K16, aw08v + (size_t)(z - 1) * K16 * FFP, FFP,
                           nullptr, nullptr,
                           (__nv_bfloat16*)uabb + (size_t)(z - 1) * KTOP * FFP, FFP,
                           K16 / BKK, KTOP, FFP, 1.f / 512.f, smem);
    }
}

// which==0: g_m = mb1 + wb1 + wpart[w] + sum(part);  which==1: g_fine = ab1 + sum(part)
__global__ void mlp_reduce(const float* __restrict__ v0, const float* __restrict__ v1,
                           int which, int R)
{
    int r = blockIdx.x * 256 + threadIdx.x;
    if (r >= R) return;
    float acc = 0.f;
    #pragma unroll
    for (int c = 0; c < NCB; c++) acc += g_part[(size_t)r * NCB + c];
    if (which) {
        g_fine[r] = v0[0] + acc;
    } else {
        int w = g_w[r] - 1;
        float base = v0[0] + v1[0];
        #pragma unroll
        for (int c = 0; c < 6; c++) base += g_wpart[w * 6 + c];
        g_m[r] = base + acc;
    }
}

// ---------------- top-K mentions: 64-bit radix select in smem ----------------
__global__ void topk_mentions(const int* __restrict__ spk, const int* __restrict__ sent)
{
    extern __shared__ unsigned long long skeys[];   // NSP keys (64 KB)
    __shared__ int hist[256];
    __shared__ int tix[256];
    __shared__ unsigned long long s_pfx;
    __shared__ int s_tgt, s_cnt;
    int tid = threadIdx.x;            // 1024
    for (int i = tid; i < NSP; i += 1024) skeys[i] = make_key(g_m[i], (unsigned)i);
    if (tid == 0) { s_tgt = KTOP; s_pfx = 0ull; s_cnt = 0; }
    __syncthreads();

    for (int byte = 7; byte >= 0; byte--) {
        int shift = byte * 8;
        if (tid < 256) hist[tid] = 0;
        __syncthreads();
        unsigned long long pfx = s_pfx;
        for (int i = tid; i < NSP; i += 1024) {
            unsigned long long k = skeys[i];
            bool match = (byte == 7) || ((k >> (shift + 8)) == (pfx >> (shift + 8)));
            if (match) atomicAdd(&hist[(int)((k >> shift) & 255)], 1);
        }
        __syncthreads();
        if (tid == 0) {
            int cum = 0, v = 255;
            for (; v > 0; v--) { if (cum + hist[v] >= s_tgt) break; cum += hist[v]; }
            s_tgt -= cum;
            s_pfx = pfx | ((unsigned long long)(unsigned)v << shift);
        }
        __syncthreads();
    }
    unsigned long long thr = s_pfx;
    for (int i = tid; i < NSP; i += 1024) {
        if (skeys[i] >= thr) {
            int pos = atomicAdd(&s_cnt, 1);
            if (pos < 256) tix[pos] = key_idx(skeys[i]);
        }
    }
    __syncthreads();
    for (int t = tid; t < 256; t += 1024) if (t >= KTOP) tix[t] = 0x7FFFFFFF;
    __syncthreads();
    for (unsigned k = 2; k <= 256; k <<= 1)
        for (unsigned j = k >> 1; j > 0; j >>= 1) {
            for (unsigned t = tid; t < 256; t += 1024) {
                unsigned ixj = t ^ j;
                if (ixj > t) {
                    int a = tix[t], b = tix[ixj];
                    bool asc = ((t & k) == 0);
                    if (asc ? (a > b) : (a < b)) { tix[t] = b; tix[ixj] = a; }
                }
            }
            __syncthreads();
        }
    if (tid < KTOP) {
        int idx = tix[tid];
        g_topidx[tid] = idx;
        g_topm[tid]   = g_m[idx];
        int s = g_s[idx];
        g_topspk[tid] = spk[s];
        g_topseg[tid] = sent[s];
    }
}

// ---------------- build top-204 base rows (bf16 + fp8 x8) ----------------
__global__ void build_topbase(const float* __restrict__ h, const float* __restrict__ width_emb)
{
    int i = blockIdx.x;               // KTOP blocks
    int tid = threadIdx.x;            // 256
    __shared__ float wts[32];
    __shared__ int shr[3];
    if (tid == 0) {
        int idx = g_topidx[i];
        shr[0] = g_s[idx]; shr[1] = g_e[idx]; shr[2] = g_w[idx];
    }
    __syncthreads();
    int s = shr[0], e = shr[1], w = shr[2];
    if (tid < 32) wts[tid] = g_wts[(size_t)g_topidx[i] * 32 + tid];
    __syncthreads();

    __nv_bfloat16* dsh = g_topbaseh + (size_t)i * KPAD;
    uint8_t* d8 = (uint8_t*)g_topb8 + (size_t)i * KPAD;
    const float* hs = h + (size_t)s * HD;
    const float* he = h + (size_t)e * HD;
    for (int c = tid; c < HD; c += 256) {
        float acc = 0.f;
        for (int wp = 0; wp < w; wp++) acc += wts[wp] * h[(size_t)(s + wp) * HD + c];
        float v0 = hs[c], v1 = he[c];
        dsh[c]          = __float2bfloat16(v0);
        dsh[HD + c]     = __float2bfloat16(v1);
        dsh[2 * HD + c] = __float2bfloat16(acc);
        d8[c]          = (uint8_t)(cvt_e4m3x2(v0 * 8.f, 0.f) & 0xFF);
        d8[HD + c]     = (uint8_t)(cvt_e4m3x2(v1 * 8.f, 0.f) & 0xFF);
        d8[2 * HD + c] = (uint8_t)(cvt_e4m3x2(acc * 8.f, 0.f) & 0xFF);
    }
    if (tid < 20) {
        float v = width_emb[(w - 1) * 20 + tid];
        dsh[3 * HD + tid] = __float2bfloat16(v);
        d8[3 * HD + tid]  = (uint8_t)(cvt_e4m3x2(v * 8.f, 0.f) & 0xFF);
    }
}

// ---------------- per-row top-C antecedents + compact fp8 pair packing ----------------
__global__ void topc_pack()
{
    int i = blockIdx.x;
    int tid = threadIdx.x;            // 256
    __shared__ unsigned long long keys[256];
    __shared__ int spos[CANT];
    if (tid < 256)
        keys[tid] = (tid < KTOP) ? make_key(g_cp[i * KTOP + tid], (unsigned)tid) : 0ull;
    __syncthreads();
    for (unsigned k = 2; k <= 256; k <<= 1)
        for (unsigned j = k >> 1; j > 0; j >>= 1) {
            unsigned t = tid;
            unsigned ixj = t ^ j;
            if (ixj > t) {
                unsigned long long a = keys[t], b = keys[ixj];
                bool desc = ((t & k) == 0);
                if (desc ? (a < b) : (a > b)) { keys[t] = b; keys[ixj] = a; }
            }
            __syncthreads();
        }
    if (tid < CANT) {
        int pos = key_idx(keys[tid]);
        spos[tid] = pos;
        g_antpos[i * CANT + tid] = pos;
        g_antsc[i * CANT + tid] = g_cp[i * KTOP + pos];
    }
    __syncthreads();

    // pack this row-block's compact fp8 pair products: rows pair_off(i)..+min(i,50)-1
    int nv = (i < CANT) ? i : CANT;
    if (nv == 0) return;
    int base_r = pair_off(i);
    const uint4* a = (const uint4*)(g_topbaseh + (size_t)i * KPAD);
    const int ROWV = KPAD / 8;        // 296 vec16 per row
    for (int idx = tid; idx < nv * ROWV; idx += 256) {
        int c = idx / ROWV, v = idx % ROWV;
        int p = spos[c];
        const uint4* b = (const uint4*)(g_topbaseh + (size_t)p * KPAD);
        uint4 va = a[v], vb = b[v];
        __nv_bfloat162* pa = (__nv_bfloat162*)&va;
        __nv_bfloat162* pb = (__nv_bfloat162*)&vb;
        uint16_t res[4];
        #pragma unroll
        for (int q = 0; q < 4; q++) {
            float2 fa = __bfloat1622float2(pa[q]);
            float2 fb = __bfloat1622float2(pb[q]);
            res[q] = cvt_e4m3x2(fa.x * fb.x, fa.y * fb.y);
        }
        *(uint64_t*)(g_pair8 + (size_t)(base_r + c) * K16 + v * 4) = *(uint64_t*)res;
    }
}

// ---------------- final output ----------------
__global__ void final_out(float* __restrict__ out, const float* __restrict__ dummy)
{
    int i = blockIdx.x;
    int tid = threadIdx.x;            // 64
    if (tid == 0) out[i * (CANT + 1)] = dummy[0];
    if (tid < CANT) {
        int nvalid = (i < CANT) ? i : CANT;
        bool valid = tid < nvalid;
        float v = NEG9;
        if (valid)
            v = g_antsc[i * CANT + tid] + g_fine[pair_off(i) + tid] * 2.0f;
        out[i * (CANT + 1) + 1 + tid] = v;
    }
}

// ---------------- launch ----------------
extern "C" void kernel_launch(void* const* d_in, const int* in_sizes, int n_in,
                              void* d_out, int out_size)
{
    const float* h          = (const float*)d_in[0];
    const int*   spans      = (const int*)  d_in[1];
    const int*   spk_ids    = (const int*)  d_in[2];
    const int*   gen_ids    = (const int*)  d_in[3];
    const int*   sent_map   = (const int*)  d_in[4];
    const float* w_head     = (const float*)d_in[5];
    const float* b_head     = (const float*)d_in[6];
    const float* width_emb  = (const float*)d_in[7];
    const float* width_prior= (const float*)d_in[8];
    const float* speaker_emb= (const float*)d_in[9];
    const float* segment_emb= (const float*)d_in[10];
    const float* genre_emb  = (const float*)d_in[11];
    const float* dist_emb   = (const float*)d_in[12];
    const float* mention_w0 = (const float*)d_in[13];
    const float* mention_b0 = (const float*)d_in[14];
    const float* mention_w1 = (const float*)d_in[15];
    const float* mention_b1 = (const float*)d_in[16];
    const float* width_w0   = (const float*)d_in[17];
    const float* width_b0   = (const float*)d_in[18];
    const float* width_w1   = (const float*)d_in[19];
    const float* width_b1   = (const float*)d_in[20];
    const float* c2_w       = (const float*)d_in[21];
    const float* c2_b       = (const float*)d_in[22];
    const float* ant_w0     = (const float*)d_in[23];
    const float* ant_b0     = (const float*)d_in[24];
    const float* ant_w1     = (const float*)d_in[25];
    const float* ant_b1     = (const float*)d_in[26];
    const float* dummy_bias = (const float*)d_in[27];
    float* out = (float*)d_out;

    cudaFuncSetAttribute((const void*)hgemm2<1,1,0>, cudaFuncAttributeMaxDynamicSharedMemorySize, DSMEM_ALL);
    cudaFuncSetAttribute((const void*)hgemm2<2,0,1>, cudaFuncAttributeMaxDynamicSharedMemorySize, DSMEM_ALL);
    cudaFuncSetAttribute((const void*)hgemm2<3,1,0>, cudaFuncAttributeMaxDynamicSharedMemorySize, DSMEM_ALL);
    cudaFuncSetAttribute((const void*)hgemm2<4,0,0>, cudaFuncAttributeMaxDynamicSharedMemorySize, DSMEM_ALL);
    cudaFuncSetAttribute((const void*)src_uab, cudaFuncAttributeMaxDynamicSharedMemorySize, DSMEM_ALL);
    cudaFuncSetAttribute(topk_mentions, cudaFuncAttributeMaxDynamicSharedMemorySize, NSP * 8);

    void *pW0h, *pAw08, *pC2h, *pPair8, *pTopbh, *pTopb8, *pUabb, *pHh, *pSw8, *pPh8, *pPb;
    void *pSrch, *pTopbT, *pCp;
    cudaGetSymbolAddress(&pW0h,   g_w0h);
    cudaGetSymbolAddress(&pAw08,  g_aw08);
    cudaGetSymbolAddress(&pC2h,   g_c2h);
    cudaGetSymbolAddress(&pPair8, g_pair8);
    cudaGetSymbolAddress(&pTopbh, g_topbaseh);
    cudaGetSymbolAddress(&pTopb8, g_topb8);
    cudaGetSymbolAddress(&pUabb,  g_uabb);
    cudaGetSymbolAddress(&pHh,    g_hh);
    cudaGetSymbolAddress(&pSw8,   g_sw8);
    cudaGetSymbolAddress(&pPh8,   g_ph8);
    cudaGetSymbolAddress(&pPb,    g_Pb);
    cudaGetSymbolAddress(&pSrch,  g_srch);
    cudaGetSymbolAddress(&pTopbT, g_topbT);
    cudaGetSymbolAddress(&pCp,    g_cp);
    const __nv_bfloat16* aw08  = (const __nv_bfloat16*)pAw08;   // b16 view of fp8 pairs
    const __nv_bfloat16* c2h   = (const __nv_bfloat16*)pC2h;
    const __nv_bfloat16* pair8 = (const __nv_bfloat16*)pPair8;  // b16 view
    const __nv_bfloat16* topbh = (const __nv_bfloat16*)pTopbh;
    const __nv_bfloat16* topb8 = (const __nv_bfloat16*)pTopb8;  // b16 view
    const __nv_bfloat16* hh    = (const __nv_bfloat16*)pHh;
    const __nv_bfloat16* sw8   = (const __nv_bfloat16*)pSw8;    // b16 view
    const __nv_bfloat16* ph8   = (const __nv_bfloat16*)pPh8;    // b16 view
    const __nv_bfloat16* srch  = (const __nv_bfloat16*)pSrch;
    const __nv_bfloat16* topbT = (const __nv_bfloat16*)pTopbT;
    const __nv_bfloat16* w0h   = (const __nv_bfloat16*)pW0h;

    // 1) all conversions + wproj + width_scores + tok_score in one launch
    mega_prep<<<S6E, 256>>>(mention_w0, ant_w0, c2_w, h, w_head, b_head,
                            width_emb, width_prior, width_w0, width_b0, width_w1);

    // 2) span softmax weights
    span_prep<<<NSP / 8, 256>>>(spans);

    // 3) P_s | P_e | P_h = h @ W0 sections -> bf16  (M=512, K=768)
    hgemm2<2,0,1><<<dim3(NCB, LEN / BM, 3), 256, DSMEM_ALL>>>(
        hh, HD, w0h, FFP, (size_t)HD * FFP, nullptr, nullptr,
        pPb, PSEC, FFP, HD / BKK, LEN, FFP, 1.f);
    conv_ph8<<<dim3(FFP / 256, SW16), 256>>>();

    // 4) mention MLP: SW(fp8) @ P_h(fp8), epilogue adds Pb_s[s]+Pb_e[e]+wmb[w-1]
    hgemm2<3,1,0><<<dim3(NCB, NSP / BM), 256, DSMEM_ALL>>>(
        sw8, SW16, ph8, FFP, 0, mention_b0, mention_w1,
        nullptr, 0, 0, SW16 / BKK, NSP, FFP, 1.f / 4096.f);
    mlp_reduce<<<(NSP + 255) / 256, 256>>>(mention_b1, width_b1, 0, NSP);

    // 5) top-K + top-base rebuild
    topk_mentions<<<1, 1024, NSP * 8>>>(spk_ids, sent_map);
    build_topbase<<<KTOP, 256>>>(h, width_emb);
    transp_topb<<<dim3(KPAD / 32, 8), dim3(32, 8)>>>();

    // 6) fused: src = top_base @ c2_w + c2_b (bf16), UA/UB = top_base @ W0a/b (fp8)
    src_uab<<<dim3(NCB, 2, 3), 256, DSMEM_ALL>>>(
        topbh, topb8, c2h, aw08, c2_b, pSrch, pUabb);

    // 7) cp = src @ top_base^T + topm_i + topm_j, tril mask
    hgemm2<4,0,0><<<dim3(2, 2, 1), 256, DSMEM_ALL>>>(
        srch, KPAD, topbT, 256, 0, nullptr, nullptr,
        pCp, 0, KTOP, KPAD / BKK, KTOP, KTOP, 1.f);

    // 8) feature tables (independent of topc; kept as R12-style separate kernels)
    //    (g_featb built from g_ftab path removed; direct from featproj+featcomb)
    {
        // featproj + featcomb exactly as R12
    }
    // featproj
    {
        extern __global__ void featproj_k(const float*, const float*, const float*,
                                          const float*, const float*);
    }
    // (declared below via real kernels)
    void featproj_launch(const float*, const float*, const float*, const float*, const float*);

    // 8a) per-table projections + combine (R12 kernels)
    // -- launched right after mega_prep chain; placed here to match R12 order
    // NOTE: actual launches below
    extern __global__ void featproj(const float*, const float*, const float*,
                                    const float*, const float*);
    extern __global__ void featcomb(const int*);
    featproj<<<22, 256>>>(ant_w0, speaker_emb, genre_emb, dist_emb, segment_emb);
    featcomb<<<60, 256>>>(gen_ids);

    // 9) top-C antecedents + fused compact fp8 pair packing
    topc_pack<<<KTOP, 256>>>();

    // 10) fine pairwise MLP (fp8, compact valid rows), scale 1/64
    hgemm2<1,1,0><<<dim3(NCB, VPAD / BM), 256, DSMEM_ALL>>>(
        pair8, K16, aw08 + 2 * (size_t)K16 * FFP, FFP, 0, ant_b0, ant_w1,
        nullptr, 0, 0, K16 / BKK, VPAD, FFP, 1.f / 64.f);
    mlp_reduce<<<(VPAD + 255) / 256, 256>>>(ant_b1, nullptr, 1, VPAD);

    final_out<<<KTOP, 64>>>(out, dummy_bias);
}

// ---------------- feature table projections (R12 kernels) ----------------
__global__ void featproj(const float* __restrict__ aw0,
                         const float* __restrict__ spk_emb, const float* __restrict__ gen_emb,
                         const float* __restrict__ dist_emb, const float* __restrict__ seg_emb)
{
    int row = blockIdx.x;             // 22
    int tid = threadIdx.x;            // 256
    const float* emb; int off;
    if (row < 2)       { emb = spk_emb  + row * 20;        off = 0; }
    else if (row < 9)  { emb = gen_emb  + (row - 2) * 20;  off = 20; }
    else if (row < 19) { emb = dist_emb + (row - 9) * 20;  off = 40; }
    else               { emb = seg_emb  + (row - 19) * 20; off = 60; }
    __shared__ float ev[20];
    if (tid < 20) ev[tid] = emb[tid];
    __syncthreads();
    for (int f = tid; f < FFP; f += 256) {
        float acc = 0.f;
        if (f < FFD) {
            #pragma unroll
            for (int k = 0; k < 20; k++)
                acc += ev[k] * aw0[(size_t)(3 * MD + off + k) * FFD + f];
        }
        g_ftab[(size_t)row * FFP + f] = acc;
    }
}

__global__ void featcomb(const int* __restrict__ gen_ids)
{
    int code = blockIdx.x;            // 60
    int tid = threadIdx.x;            // 256
    int s = code / 30, bk = (code / 3) % 10, ds = code % 3;
    int g = gen_ids[0];
    for (int f = tid; f < FFP; f += 256)
        g_featb[(size_t)code * FFP + f] = __float2bfloat16(
            g_ftab[(size_t)s * FFP + f] + g_ftab[(size_t)(2 + g) * FFP + f] +
            g_ftab[(size_t)(9 + bk) * FFP + f] + g_ftab[(size_t)(19 + ds) * FFP + f]);
}